// round 2
// baseline (speedup 1.0000x reference)
#include <cuda_runtime.h>
#include <math.h>

#define BB 64
#define SS 100
#define EE 512
#define HH 1024
#define VT 32000

// ---------------- scratch ----------------
__device__ float g_enc[(size_t)BB * SS * HH];   // [B,S,H] combined embeddings
__device__ float g_mean[BB * HH];               // mean over S
__device__ float g_h0[BB * HH];                 // encoder hidden
__device__ float g_ctx[BB * HH];                // attention context
__device__ float g_x[BB * (EE + HH)];           // decoder input concat

// ---------------- 1. build enc = [emb_in[src] | emb_pos[pos]] ----------------
__global__ __launch_bounds__(128) void build_enc_kernel(
    const int* __restrict__ src, const int* __restrict__ pos,
    const float* __restrict__ emb_in, const float* __restrict__ emb_pos)
{
    int bs = blockIdx.x;           // 0..B*S-1
    int t  = threadIdx.x;          // 0..127
    const float4* wi = (const float4*)(emb_in  + (size_t)src[bs] * EE);
    const float4* wp = (const float4*)(emb_pos + (size_t)pos[bs] * EE);
    float4* dst = (float4*)(g_enc + (size_t)bs * HH);
    dst[t]       = wi[t];          // 128 float4 = 512 floats
    dst[128 + t] = wp[t];
}

// ---------------- 2. mean over S ----------------
__global__ __launch_bounds__(256) void mean_kernel()
{
    int b  = blockIdx.x;
    int c4 = threadIdx.x * 4;
    float4 acc = make_float4(0.f, 0.f, 0.f, 0.f);
    const float* base = g_enc + (size_t)b * SS * HH + c4;
    for (int s = 0; s < SS; s++) {
        float4 v = *(const float4*)(base + (size_t)s * HH);
        acc.x += v.x; acc.y += v.y; acc.z += v.z; acc.w += v.w;
    }
    const float inv = 1.0f / SS;
    acc.x *= inv; acc.y *= inv; acc.z *= inv; acc.w *= inv;
    *(float4*)(g_mean + b * HH + c4) = acc;
}

// ---------------- generic M=64 SGEMM: C[64,N] = sum_seg A@B^T + bias ----------------
// A: [64,K] row-major. B: [N,K] row-major. Optional 2nd segment, optional tanh.
__global__ __launch_bounds__(256) void gemm64_kernel(
    const float* __restrict__ A0, const float* __restrict__ B0, int K0,
    const float* __restrict__ A1, const float* __restrict__ B1, int K1,
    const float* __restrict__ bias0, const float* __restrict__ bias1,
    float* __restrict__ C, int N, int do_tanh)
{
    __shared__ float As[16][64];
    __shared__ float Bs[16][128];

    const int tid = threadIdx.x;
    const int tx  = tid & 15;    // n-group: 16 groups of 8 cols
    const int ty  = tid >> 4;    // m-group: 16 groups of 4 rows
    const int n0  = blockIdx.x * 128;

    float acc[4][8];
    #pragma unroll
    for (int i = 0; i < 4; i++)
        #pragma unroll
        for (int j = 0; j < 8; j++) acc[i][j] = 0.f;

    const int ldm = tid >> 2;    // 0..63
    const int ldf = tid & 3;     // 0..3

    for (int seg = 0; seg < 2; seg++) {
        const float* A  = seg ? A1 : A0;
        const float* Bm = seg ? B1 : B0;
        const int    K  = seg ? K1 : K0;
        if (A == nullptr) continue;
        for (int kk = 0; kk < K; kk += 16) {
            // A tile: 64 rows x 16 k
            {
                float4 v = *(const float4*)&A[(size_t)ldm * K + kk + ldf * 4];
                As[ldf*4+0][ldm] = v.x; As[ldf*4+1][ldm] = v.y;
                As[ldf*4+2][ldm] = v.z; As[ldf*4+3][ldm] = v.w;
            }
            // B tile: 128 rows x 16 k
            {
                float4 v0 = *(const float4*)&Bm[(size_t)(n0 + ldm) * K + kk + ldf * 4];
                float4 v1 = *(const float4*)&Bm[(size_t)(n0 + ldm + 64) * K + kk + ldf * 4];
                Bs[ldf*4+0][ldm]    = v0.x; Bs[ldf*4+1][ldm]    = v0.y;
                Bs[ldf*4+2][ldm]    = v0.z; Bs[ldf*4+3][ldm]    = v0.w;
                Bs[ldf*4+0][ldm+64] = v1.x; Bs[ldf*4+1][ldm+64] = v1.y;
                Bs[ldf*4+2][ldm+64] = v1.z; Bs[ldf*4+3][ldm+64] = v1.w;
            }
            __syncthreads();
            #pragma unroll
            for (int k = 0; k < 16; k++) {
                float4 a  = *(const float4*)&As[k][ty * 4];
                float4 b0 = *(const float4*)&Bs[k][tx * 8];
                float4 b1 = *(const float4*)&Bs[k][tx * 8 + 4];
                float am[4] = {a.x, a.y, a.z, a.w};
                float bn[8] = {b0.x, b0.y, b0.z, b0.w, b1.x, b1.y, b1.z, b1.w};
                #pragma unroll
                for (int i = 0; i < 4; i++)
                    #pragma unroll
                    for (int j = 0; j < 8; j++)
                        acc[i][j] = fmaf(am[i], bn[j], acc[i][j]);
            }
            __syncthreads();
        }
    }

    // epilogue
    #pragma unroll
    for (int i = 0; i < 4; i++) {
        int m = ty * 4 + i;
        #pragma unroll
        for (int j0 = 0; j0 < 8; j0 += 4) {
            int n = n0 + tx * 8 + j0;
            float4 v;
            float vb[4];
            #pragma unroll
            for (int j = 0; j < 4; j++) {
                float val = acc[i][j0 + j] + bias0[n + j];
                if (bias1) val += bias1[n + j];
                if (do_tanh) val = tanhf(val);
                vb[j] = val;
            }
            v.x = vb[0]; v.y = vb[1]; v.z = vb[2]; v.w = vb[3];
            *(float4*)&C[(size_t)m * N + n] = v;
        }
    }
}

// ---------------- 4. attention: energy -> softmax -> context (with 1/S mean) ----------------
__global__ __launch_bounds__(256) void attention_kernel(float* __restrict__ ctx)
{
    __shared__ float h0s[HH];
    __shared__ float en[SS];

    int b    = blockIdx.x;
    int tid  = threadIdx.x;
    int warp = tid >> 5;
    int lane = tid & 31;

    for (int c = tid; c < HH; c += 256) h0s[c] = g_h0[b * HH + c];
    __syncthreads();

    // energies: one warp per s
    for (int s = warp; s < SS; s += 8) {
        const float* row = g_enc + ((size_t)b * SS + s) * HH;
        float sum = 0.f;
        for (int e = lane; e < HH; e += 32) sum = fmaf(h0s[e], row[e], sum);
        #pragma unroll
        for (int o = 16; o; o >>= 1) sum += __shfl_xor_sync(0xffffffffu, sum, o);
        if (lane == 0) en[s] = sum;
    }
    __syncthreads();

    // softmax over S (warp 0), fold 1/S of the mean into the weights
    if (warp == 0) {
        float m = -1e30f;
        for (int s = lane; s < SS; s += 32) m = fmaxf(m, en[s]);
        #pragma unroll
        for (int o = 16; o; o >>= 1) m = fmaxf(m, __shfl_xor_sync(0xffffffffu, m, o));
        float sum = 0.f;
        for (int s = lane; s < SS; s += 32) {
            float v = __expf(en[s] - m);
            en[s] = v;
            sum += v;
        }
        #pragma unroll
        for (int o = 16; o; o >>= 1) sum += __shfl_xor_sync(0xffffffffu, sum, o);
        float inv = 1.0f / (sum * (float)SS);
        for (int s = lane; s < SS; s += 32) en[s] *= inv;
    }
    __syncthreads();

    // context accumulation: each thread owns 4 channels
    int c4 = tid * 4;
    float4 acc = make_float4(0.f, 0.f, 0.f, 0.f);
    const float* base = g_enc + (size_t)b * SS * HH + c4;
    for (int s = 0; s < SS; s++) {
        float w = en[s];
        float4 v = *(const float4*)(base + (size_t)s * HH);
        acc.x = fmaf(w, v.x, acc.x); acc.y = fmaf(w, v.y, acc.y);
        acc.z = fmaf(w, v.z, acc.z); acc.w = fmaf(w, v.w, acc.w);
    }
    *(float4*)(ctx + b * HH + c4) = acc;
}

// ---------------- 5. build x = [emb_out[tgt] | ctx] ----------------
__global__ __launch_bounds__(256) void build_x_kernel(
    const int* __restrict__ tgt, const float* __restrict__ emb_out)
{
    int b = blockIdx.x;
    int t = threadIdx.x;
    const float4* w = (const float4*)(emb_out + (size_t)tgt[b] * EE);
    const float4* c = (const float4*)(g_ctx + b * HH);
    float4* dst = (float4*)(g_x + b * (EE + HH));
    if (t < 128) dst[t] = w[t];            // 512 floats
    dst[128 + t] = c[t];                   // 1024 floats
}

// ---------------- launch ----------------
extern "C" void kernel_launch(void* const* d_in, const int* in_sizes, int n_in,
                              void* d_out, int out_size)
{
    // fixed leading indices
    const int* src = (const int*)d_in[0];
    const int* pos = (const int*)d_in[1];
    const int* tgt = (const int*)d_in[2];

    // locate emb_in by its size, robust to scalar-input packing
    int iE = -1;
    for (int i = 3; i < n_in; i++) {
        if (in_sizes[i] == 32000 * 512) { iE = i; break; }
    }
    const float* emb_in  = (const float*)d_in[iE + 0];
    const float* emb_out = (const float*)d_in[iE + 1];
    const float* emb_pos = (const float*)d_in[iE + 2];
    const float* W_scale = (const float*)d_in[iE + 3];
    const float* b_scale = (const float*)d_in[iE + 4];
    const float* W_ih    = (const float*)d_in[iE + 5];
    const float* b_ih    = (const float*)d_in[iE + 6];
    const float* W_hh    = (const float*)d_in[iE + 7];
    const float* b_hh    = (const float*)d_in[iE + 8];
    const float* W_proj  = (const float*)d_in[iE + 9];
    const float* b_proj  = (const float*)d_in[iE + 10];

    float* out = (float*)d_out;            // [B,VT]
    float* h   = out + (size_t)BB * VT;    // [B,H]

    float* g_enc_p, *g_mean_p, *g_h0_p, *g_ctx_p, *g_x_p;
    cudaGetSymbolAddress((void**)&g_enc_p,  g_enc);
    cudaGetSymbolAddress((void**)&g_mean_p, g_mean);
    cudaGetSymbolAddress((void**)&g_h0_p,   g_h0);
    cudaGetSymbolAddress((void**)&g_ctx_p,  g_ctx);
    cudaGetSymbolAddress((void**)&g_x_p,    g_x);

    // 1. build enc
    build_enc_kernel<<<BB * SS, 128>>>(src, pos, emb_in, emb_pos);
    // 2. mean over S
    mean_kernel<<<BB, 256>>>();
    // 3. h0 = mean @ W_scale^T + b_scale
    gemm64_kernel<<<HH / 128, 256>>>(g_mean_p, W_scale, HH,
                                     nullptr, nullptr, 0,
                                     b_scale, nullptr,
                                     g_h0_p, HH, 0);
    // 4. attention -> ctx
    attention_kernel<<<BB, 256>>>(g_ctx_p);
    // 5. x = [emb_out[tgt] | ctx]
    build_x_kernel<<<BB, 256>>>(tgt, emb_out);
    // 6. h = tanh(x @ W_ih^T + h0 @ W_hh^T + b_ih + b_hh)
    gemm64_kernel<<<HH / 128, 256>>>(g_x_p, W_ih, EE + HH,
                                     g_h0_p, W_hh, HH,
                                     b_ih, b_hh,
                                     h, HH, 1);
    // 7. out = h @ W_proj^T + b_proj
    gemm64_kernel<<<VT / 128, 256>>>(h, W_proj, HH,
                                     nullptr, nullptr, 0,
                                     b_proj, nullptr,
                                     out, VT, 0);
    (void)out_size;
}

// round 4
// speedup vs baseline: 5.9178x; 5.9178x over previous
#include <cuda_runtime.h>
#include <math.h>
#include <stdint.h>

#define BB 64
#define SS 100
#define EE 512
#define HH 1024
#define VT 32000
#define NSPLIT 8
#define SCH 4            // s-chunks for mean/context partials

// ---------------- scratch ----------------
__device__ float g_enc[(size_t)BB * SS * HH];   // [B,S,H] combined embeddings
__device__ float g_mpart[SCH * BB * HH];        // mean partials
__device__ float g_mean[BB * HH];
__device__ float g_h0[BB * HH];
__device__ float g_en[BB * SS];                 // energies
__device__ float g_att[BB * SS];                // softmax weights (incl. 1/S)
__device__ float g_cpart[SCH * BB * HH];        // context partials
__device__ float g_x[BB * (EE + HH)];           // decoder input concat
__device__ float g_part[NSPLIT * BB * HH];      // split-K partials

// ---------------- helpers ----------------
__device__ __forceinline__ uint32_t smem_u32(const void* p) {
    uint32_t a;
    asm("{ .reg .u64 t; cvta.to.shared.u64 t, %1; cvt.u32.u64 %0, t; }" : "=r"(a) : "l"(p));
    return a;
}
__device__ __forceinline__ uint32_t f2tf32(float x) {
    uint32_t u;
    asm("cvt.rna.tf32.f32 %0, %1;" : "=r"(u) : "f"(x));
    return u;
}
__device__ __forceinline__ void cp_async16(uint32_t saddr, const void* g) {
    asm volatile("cp.async.ca.shared.global [%0], [%1], 16;" :: "r"(saddr), "l"(g) : "memory");
}
__device__ __forceinline__ void cp_commit() {
    asm volatile("cp.async.commit_group;" ::: "memory");
}
__device__ __forceinline__ void cp_wait1() {
    asm volatile("cp.async.wait_group 1;" ::: "memory");
}
__device__ __forceinline__ void mma_tf32(float d[4], const uint32_t a[4], const uint32_t b[2]) {
    asm volatile(
        "mma.sync.aligned.m16n8k8.row.col.f32.tf32.tf32.f32 "
        "{%0,%1,%2,%3}, {%4,%5,%6,%7}, {%8,%9}, {%0,%1,%2,%3};"
        : "+f"(d[0]), "+f"(d[1]), "+f"(d[2]), "+f"(d[3])
        : "r"(a[0]), "r"(a[1]), "r"(a[2]), "r"(a[3]), "r"(b[0]), "r"(b[1]));
}

// ---------------- 1. build enc = [emb_in[src] | emb_pos[pos]] ----------------
__global__ __launch_bounds__(128) void build_enc_kernel(
    const int* __restrict__ src, const int* __restrict__ pos,
    const float* __restrict__ emb_in, const float* __restrict__ emb_pos)
{
    int bs = blockIdx.x;
    int t  = threadIdx.x;
    const float4* wi = (const float4*)(emb_in  + (size_t)src[bs] * EE);
    const float4* wp = (const float4*)(emb_pos + (size_t)pos[bs] * EE);
    float4* dst = (float4*)(g_enc + (size_t)bs * HH);
    dst[t]       = wi[t];
    dst[128 + t] = wp[t];
}

// ---------------- 2a. mean partials over s-chunks ----------------
__global__ __launch_bounds__(256) void mean_part_kernel()
{
    int b  = blockIdx.x;
    int y  = blockIdx.y;
    int c4 = threadIdx.x * 4;
    float4 acc = make_float4(0.f, 0.f, 0.f, 0.f);
    const float* base = g_enc + (size_t)b * SS * HH + c4;
    #pragma unroll 5
    for (int s = y * (SS / SCH); s < (y + 1) * (SS / SCH); s++) {
        float4 v = *(const float4*)(base + (size_t)s * HH);
        acc.x += v.x; acc.y += v.y; acc.z += v.z; acc.w += v.w;
    }
    *(float4*)(g_mpart + ((size_t)y * BB + b) * HH + c4) = acc;
}
// ---------------- 2b. mean reduce ----------------
__global__ __launch_bounds__(256) void mean_red_kernel()
{
    int b  = blockIdx.x;
    int c4 = threadIdx.x * 4;
    float4 s = make_float4(0.f, 0.f, 0.f, 0.f);
    #pragma unroll
    for (int y = 0; y < SCH; y++) {
        float4 v = *(const float4*)(g_mpart + ((size_t)y * BB + b) * HH + c4);
        s.x += v.x; s.y += v.y; s.z += v.z; s.w += v.w;
    }
    const float inv = 1.0f / SS;
    s.x *= inv; s.y *= inv; s.z *= inv; s.w *= inv;
    *(float4*)(g_mean + b * HH + c4) = s;
}

// ---------------- split-K SGEMM: part[split][64][N] = A@B^T slice ----------------
__global__ __launch_bounds__(256) void gemm64sk_kernel(
    const float* __restrict__ A0, const float* __restrict__ B0, int K0,
    const float* __restrict__ A1, const float* __restrict__ B1, int K1,
    float* __restrict__ part, int N, int kslice)
{
    __shared__ float As[16][64];
    __shared__ float Bs[16][64];
    const int tid = threadIdx.x;
    const int tx  = tid & 15;
    const int ty  = tid >> 4;
    const int n0  = blockIdx.x * 64;
    const int kbase = blockIdx.y * kslice;

    float acc[4][4];
    #pragma unroll
    for (int i = 0; i < 4; i++)
        #pragma unroll
        for (int j = 0; j < 4; j++) acc[i][j] = 0.f;

    const int lr = tid >> 2;
    const int lf = tid & 3;

    for (int kk = 0; kk < kslice; kk += 16) {
        int g = kbase + kk;
        const float* A; const float* Bm; int K; int kl;
        if (g < K0) { A = A0; Bm = B0; K = K0; kl = g; }
        else        { A = A1; Bm = B1; K = K1; kl = g - K0; }
        float4 va = *(const float4*)&A[(size_t)lr * K + kl + lf * 4];
        float4 vb = *(const float4*)&Bm[(size_t)(n0 + lr) * K + kl + lf * 4];
        __syncthreads();
        As[lf*4+0][lr] = va.x; As[lf*4+1][lr] = va.y;
        As[lf*4+2][lr] = va.z; As[lf*4+3][lr] = va.w;
        Bs[lf*4+0][lr] = vb.x; Bs[lf*4+1][lr] = vb.y;
        Bs[lf*4+2][lr] = vb.z; Bs[lf*4+3][lr] = vb.w;
        __syncthreads();
        #pragma unroll
        for (int k = 0; k < 16; k++) {
            float4 a = *(const float4*)&As[k][ty * 4];
            float4 b = *(const float4*)&Bs[k][tx * 4];
            float am[4] = {a.x, a.y, a.z, a.w};
            float bn[4] = {b.x, b.y, b.z, b.w};
            #pragma unroll
            for (int i = 0; i < 4; i++)
                #pragma unroll
                for (int j = 0; j < 4; j++)
                    acc[i][j] = fmaf(am[i], bn[j], acc[i][j]);
        }
    }

    float* dst = part + (size_t)blockIdx.y * 64 * N;
    #pragma unroll
    for (int i = 0; i < 4; i++) {
        int m = ty * 4 + i;
        float4 v = make_float4(acc[i][0], acc[i][1], acc[i][2], acc[i][3]);
        *(float4*)&dst[(size_t)m * N + n0 + tx * 4] = v;
    }
}

// ---------------- reduce partials + bias (+bias1) (+tanh) ----------------
__global__ __launch_bounds__(256) void reduce_part_kernel(
    const float* __restrict__ bias0, const float* __restrict__ bias1,
    float* __restrict__ C, int N, int do_tanh)
{
    int idx = blockIdx.x * 256 + threadIdx.x;
    int nq = N >> 2;
    int m  = idx / nq;
    int n4 = idx - m * nq;
    float4 s = make_float4(0.f, 0.f, 0.f, 0.f);
    #pragma unroll
    for (int p = 0; p < NSPLIT; p++) {
        float4 v = *(const float4*)&g_part[((size_t)p * 64 + m) * N + n4 * 4];
        s.x += v.x; s.y += v.y; s.z += v.z; s.w += v.w;
    }
    float4 b0 = *(const float4*)&bias0[n4 * 4];
    s.x += b0.x; s.y += b0.y; s.z += b0.z; s.w += b0.w;
    if (bias1) {
        float4 b1 = *(const float4*)&bias1[n4 * 4];
        s.x += b1.x; s.y += b1.y; s.z += b1.z; s.w += b1.w;
    }
    if (do_tanh) {
        s.x = tanhf(s.x); s.y = tanhf(s.y); s.z = tanhf(s.z); s.w = tanhf(s.w);
    }
    *(float4*)&C[(size_t)m * N + n4 * 4] = s;
}

// ---------------- 4a. energies ----------------
__global__ __launch_bounds__(256) void energy_kernel()
{
    __shared__ float h0s[HH];
    int b    = blockIdx.x;
    int tid  = threadIdx.x;
    int warp = tid >> 5;
    int lane = tid & 31;

    for (int c = tid; c < HH; c += 256) h0s[c] = g_h0[b * HH + c];
    __syncthreads();

    int s = blockIdx.y * 8 + warp;
    if (s < SS) {
        const float4* row = (const float4*)(g_enc + ((size_t)b * SS + s) * HH);
        float sum = 0.f;
        #pragma unroll
        for (int e = 0; e < 8; e++) {
            float4 v = row[lane + e * 32];
            int c = (lane + e * 32) * 4;
            sum = fmaf(h0s[c],   v.x, sum);
            sum = fmaf(h0s[c+1], v.y, sum);
            sum = fmaf(h0s[c+2], v.z, sum);
            sum = fmaf(h0s[c+3], v.w, sum);
        }
        #pragma unroll
        for (int o = 16; o; o >>= 1) sum += __shfl_xor_sync(0xffffffffu, sum, o);
        if (lane == 0) g_en[b * SS + s] = sum;
    }
}

// ---------------- 4b. softmax (weights include 1/S for the mean) ----------------
__global__ __launch_bounds__(32) void softmax_kernel()
{
    int b    = blockIdx.x;
    int lane = threadIdx.x;
    float e[4];
    float m = -1e30f;
    #pragma unroll
    for (int i = 0; i < 4; i++) {
        int s = lane + i * 32;
        e[i] = (s < SS) ? g_en[b * SS + s] : -1e30f;
        m = fmaxf(m, e[i]);
    }
    #pragma unroll
    for (int o = 16; o; o >>= 1) m = fmaxf(m, __shfl_xor_sync(0xffffffffu, m, o));
    float sum = 0.f;
    #pragma unroll
    for (int i = 0; i < 4; i++) {
        e[i] = __expf(e[i] - m);
        sum += e[i];
    }
    #pragma unroll
    for (int o = 16; o; o >>= 1) sum += __shfl_xor_sync(0xffffffffu, sum, o);
    float inv = 1.0f / (sum * (float)SS);
    #pragma unroll
    for (int i = 0; i < 4; i++) {
        int s = lane + i * 32;
        if (s < SS) g_att[b * SS + s] = e[i] * inv;
    }
}

// ---------------- 4c. context partials ----------------
__global__ __launch_bounds__(256) void ctx_part_kernel()
{
    int b  = blockIdx.x;
    int y  = blockIdx.y;
    int c4 = threadIdx.x * 4;
    float4 acc = make_float4(0.f, 0.f, 0.f, 0.f);
    const float* base = g_enc + (size_t)b * SS * HH + c4;
    const float* w = g_att + b * SS;
    #pragma unroll 5
    for (int s = y * (SS / SCH); s < (y + 1) * (SS / SCH); s++) {
        float ws = w[s];
        float4 v = *(const float4*)(base + (size_t)s * HH);
        acc.x = fmaf(ws, v.x, acc.x); acc.y = fmaf(ws, v.y, acc.y);
        acc.z = fmaf(ws, v.z, acc.z); acc.w = fmaf(ws, v.w, acc.w);
    }
    *(float4*)(g_cpart + ((size_t)y * BB + b) * HH + c4) = acc;
}

// ---------------- 5. build x = [emb_out[tgt] | sum ctx partials] ----------------
__global__ __launch_bounds__(256) void build_x_kernel(
    const int* __restrict__ tgt, const float* __restrict__ emb_out)
{
    int b = blockIdx.x;
    int t = threadIdx.x;
    float4* dst = (float4*)(g_x + b * (EE + HH));
    if (t < 128) {
        const float4* w = (const float4*)(emb_out + (size_t)tgt[b] * EE);
        dst[t] = w[t];
    }
    float4 s = make_float4(0.f, 0.f, 0.f, 0.f);
    #pragma unroll
    for (int y = 0; y < SCH; y++) {
        float4 v = *(const float4*)(g_cpart + ((size_t)y * BB + b) * HH + t * 4);
        s.x += v.x; s.y += v.y; s.z += v.z; s.w += v.w;
    }
    dst[128 + t] = s;
}

// ---------------- 7. projection via mma.sync tf32 ----------------
// C[64,VT] = A[64,1024] @ W^T + bias.  BM=64 BN=128 BK=32, double buffered cp.async.
#define PLDA 36                      // padded row stride (floats)
#define PBUF (64 * PLDA + 128 * PLDA)  // 6912 floats per buffer
#define PROJ_SMEM (2 * PBUF * 4)       // 55296 bytes

__global__ __launch_bounds__(256, 1) void proj_mma_kernel(
    const float* __restrict__ A, const float* __restrict__ Bm,
    const float* __restrict__ bias, float* __restrict__ C)
{
    extern __shared__ float sm[];
    const int tid  = threadIdx.x;
    const int wid  = tid >> 5;
    const int lane = tid & 31;
    const int n0   = blockIdx.x * 128;
    const int wm   = wid & 1;        // warp m: 0..1 (32 rows each)
    const int wn   = wid >> 1;       // warp n: 0..3 (32 cols each)

    // per-thread load slots: A 2 x float4, B 4 x float4
    const int lrow = tid >> 3;       // 0..31
    const int lf4  = tid & 7;        // 0..7

    float d[2][4][4];
    #pragma unroll
    for (int i = 0; i < 2; i++)
        #pragma unroll
        for (int j = 0; j < 4; j++)
            #pragma unroll
            for (int k = 0; k < 4; k++) d[i][j][k] = 0.f;

    auto load_tile = [&](int buf, int kb) {
        float* as = sm + buf * PBUF;
        float* bs = as + 64 * PLDA;
        #pragma unroll
        for (int i = 0; i < 2; i++) {
            int row = lrow + i * 32;                 // 0..63
            cp_async16(smem_u32(&as[row * PLDA + lf4 * 4]),
                       &A[(size_t)row * HH + kb + lf4 * 4]);
        }
        #pragma unroll
        for (int i = 0; i < 4; i++) {
            int row = lrow + i * 32;                 // 0..127
            cp_async16(smem_u32(&bs[row * PLDA + lf4 * 4]),
                       &Bm[(size_t)(n0 + row) * HH + kb + lf4 * 4]);
        }
        cp_commit();
    };

    load_tile(0, 0);

    const int NT = HH / 32;                           // 32 tiles
    for (int t = 0; t < NT; t++) {
        if (t + 1 < NT) load_tile((t + 1) & 1, (t + 1) * 32);
        else cp_commit();                             // empty group keeps wait_group 1 correct
        cp_wait1();
        __syncthreads();

        const float* as = sm + (t & 1) * PBUF;
        const float* bs = as + 64 * PLDA;
        const int r = lane >> 2, c = lane & 3;
        #pragma unroll
        for (int k8 = 0; k8 < 4; k8++) {
            int kc = k8 * 8;
            uint32_t af[2][4], bf[4][2];
            #pragma unroll
            for (int mm = 0; mm < 2; mm++) {
                int mb = wm * 32 + mm * 16;
                af[mm][0] = f2tf32(as[(mb + r)     * PLDA + kc + c]);
                af[mm][1] = f2tf32(as[(mb + r + 8) * PLDA + kc + c]);
                af[mm][2] = f2tf32(as[(mb + r)     * PLDA + kc + c + 4]);
                af[mm][3] = f2tf32(as[(mb + r + 8) * PLDA + kc + c + 4]);
            }
            #pragma unroll
            for (int nn = 0; nn < 4; nn++) {
                int nb = wn * 32 + nn * 8;
                bf[nn][0] = f2tf32(bs[(nb + r) * PLDA + kc + c]);
                bf[nn][1] = f2tf32(bs[(nb + r) * PLDA + kc + c + 4]);
            }
            #pragma unroll
            for (int mm = 0; mm < 2; mm++)
                #pragma unroll
                for (int nn = 0; nn < 4; nn++)
                    mma_tf32(d[mm][nn], af[mm], bf[nn]);
        }
        __syncthreads();
    }

    // epilogue
    #pragma unroll
    for (int mm = 0; mm < 2; mm++) {
        int m = wm * 32 + mm * 16 + (lane >> 2);
        #pragma unroll
        for (int nn = 0; nn < 4; nn++) {
            int n = n0 + wn * 32 + nn * 8 + (lane & 3) * 2;
            float2 bv = *(const float2*)&bias[n];
            float2 o0 = make_float2(d[mm][nn][0] + bv.x, d[mm][nn][1] + bv.y);
            float2 o1 = make_float2(d[mm][nn][2] + bv.x, d[mm][nn][3] + bv.y);
            *(float2*)&C[(size_t)m * VT + n]       = o0;
            *(float2*)&C[(size_t)(m + 8) * VT + n] = o1;
        }
    }
}

// ---------------- launch ----------------
extern "C" void kernel_launch(void* const* d_in, const int* in_sizes, int n_in,
                              void* d_out, int out_size)
{
    const int* src = (const int*)d_in[0];
    const int* pos = (const int*)d_in[1];
    const int* tgt = (const int*)d_in[2];

    int iE = -1;
    for (int i = 3; i < n_in; i++) {
        if (in_sizes[i] == 32000 * 512) { iE = i; break; }
    }
    const float* emb_in  = (const float*)d_in[iE + 0];
    const float* emb_out = (const float*)d_in[iE + 1];
    const float* emb_pos = (const float*)d_in[iE + 2];
    const float* W_scale = (const float*)d_in[iE + 3];
    const float* b_scale = (const float*)d_in[iE + 4];
    const float* W_ih    = (const float*)d_in[iE + 5];
    const float* b_ih    = (const float*)d_in[iE + 6];
    const float* W_hh    = (const float*)d_in[iE + 7];
    const float* b_hh    = (const float*)d_in[iE + 8];
    const float* W_proj  = (const float*)d_in[iE + 9];
    const float* b_proj  = (const float*)d_in[iE + 10];

    float* out = (float*)d_out;            // [B,VT]
    float* h   = out + (size_t)BB * VT;    // [B,H]

    float* g_mean_p, *g_x_p, *g_part_p, *g_h0_p;
    cudaGetSymbolAddress((void**)&g_mean_p, g_mean);
    cudaGetSymbolAddress((void**)&g_h0_p,   g_h0);
    cudaGetSymbolAddress((void**)&g_x_p,    g_x);
    cudaGetSymbolAddress((void**)&g_part_p, g_part);

    cudaFuncSetAttribute(proj_mma_kernel,
                         cudaFuncAttributeMaxDynamicSharedMemorySize, PROJ_SMEM);

    // 1. build enc
    build_enc_kernel<<<BB * SS, 128>>>(src, pos, emb_in, emb_pos);
    // 2. mean over S (partials + reduce)
    mean_part_kernel<<<dim3(BB, SCH), 256>>>();
    mean_red_kernel<<<BB, 256>>>();
    // 3. h0 = mean @ W_scale^T + b_scale (split-K SIMT)
    gemm64sk_kernel<<<dim3(HH / 64, NSPLIT), 256>>>(g_mean_p, W_scale, HH,
                                                    nullptr, nullptr, 0,
                                                    g_part_p, HH, HH / NSPLIT);
    reduce_part_kernel<<<(64 * HH / 4) / 256, 256>>>(b_scale, nullptr, g_h0_p, HH, 0);
    // 4. attention
    energy_kernel<<<dim3(BB, (SS + 7) / 8), 256>>>();
    softmax_kernel<<<BB, 32>>>();
    ctx_part_kernel<<<dim3(BB, SCH), 256>>>();
    // 5. x = [emb_out[tgt] | ctx]
    build_x_kernel<<<BB, 256>>>(tgt, emb_out);
    // 6. h = tanh(x @ W_ih^T + h0 @ W_hh^T + b) (split-K SIMT)
    gemm64sk_kernel<<<dim3(HH / 64, NSPLIT), 256>>>(g_x_p, W_ih, EE + HH,
                                                    g_h0_p, W_hh, HH,
                                                    g_part_p, HH, (EE + HH + HH) / NSPLIT);
    reduce_part_kernel<<<(64 * HH / 4) / 256, 256>>>(b_ih, b_hh, h, HH, 1);
    // 7. out = h @ W_proj^T + b_proj (tf32 mma.sync)
    proj_mma_kernel<<<VT / 128, 256, PROJ_SMEM>>>(h, W_proj, b_proj, out);

    (void)out_size;
}

// round 5
// speedup vs baseline: 7.0923x; 1.1985x over previous
#include <cuda_runtime.h>
#include <math.h>
#include <stdint.h>

#define BB 64
#define SS 100
#define EE 512
#define HH 1024
#define VT 32000
#define NSPLIT 16
#define SCH 4            // s-chunks for mean/context partials

// ---------------- scratch ----------------
__device__ float g_mpart[SCH * BB * HH];        // mean partials
__device__ float g_mean[BB * HH];
__device__ float g_h0[BB * HH];
__device__ float g_en[BB * SS];                 // energies
__device__ float g_cpart[SCH * BB * HH];        // context partials
__device__ float g_x[BB * (EE + HH)];           // decoder input concat
__device__ float g_part[NSPLIT * BB * HH];      // split-K partials

// ---------------- helpers ----------------
__device__ __forceinline__ uint32_t smem_u32(const void* p) {
    uint32_t a;
    asm("{ .reg .u64 t; cvta.to.shared.u64 t, %1; cvt.u32.u64 %0, t; }" : "=r"(a) : "l"(p));
    return a;
}
__device__ __forceinline__ uint32_t f2tf32(float x) {
    uint32_t u;
    asm("cvt.rna.tf32.f32 %0, %1;" : "=r"(u) : "f"(x));
    return u;
}
__device__ __forceinline__ void cp_async16(uint32_t saddr, const void* g) {
    asm volatile("cp.async.ca.shared.global [%0], [%1], 16;" :: "r"(saddr), "l"(g) : "memory");
}
__device__ __forceinline__ void cp_commit() {
    asm volatile("cp.async.commit_group;" ::: "memory");
}
__device__ __forceinline__ void cp_wait1() {
    asm volatile("cp.async.wait_group 1;" ::: "memory");
}
__device__ __forceinline__ void cp_wait3() {
    asm volatile("cp.async.wait_group 3;" ::: "memory");
}
__device__ __forceinline__ void mma_tf32(float d[4], const uint32_t a[4], const uint32_t b[2]) {
    asm volatile(
        "mma.sync.aligned.m16n8k8.row.col.f32.tf32.tf32.f32 "
        "{%0,%1,%2,%3}, {%4,%5,%6,%7}, {%8,%9}, {%0,%1,%2,%3};"
        : "+f"(d[0]), "+f"(d[1]), "+f"(d[2]), "+f"(d[3])
        : "r"(a[0]), "r"(a[1]), "r"(a[2]), "r"(a[3]), "r"(b[0]), "r"(b[1]));
}

// ---------------- 2a. mean partials (gather directly from embeddings) ----------------
__global__ __launch_bounds__(256) void mean_part_kernel(
    const int* __restrict__ src, const int* __restrict__ pos,
    const float* __restrict__ emb_in, const float* __restrict__ emb_pos)
{
    __shared__ int sidx[32], pidx[32];
    int b   = blockIdx.x;
    int y   = blockIdx.y;
    int tid = threadIdx.x;
    int s0  = y * (SS / SCH);
    if (tid >= 32 && tid < 32 + SS / SCH) sidx[tid - 32] = src[b * SS + s0 + tid - 32];
    if (tid >= 64 && tid < 64 + SS / SCH) pidx[tid - 64] = pos[b * SS + s0 + tid - 64];
    __syncthreads();

    const int half = tid >= 128;
    const int cc = half ? tid * 4 - EE : tid * 4;
    const float* base = half ? emb_pos : emb_in;
    const int* idx = half ? pidx : sidx;
    float4 acc = make_float4(0.f, 0.f, 0.f, 0.f);
    #pragma unroll 5
    for (int i = 0; i < SS / SCH; i++) {
        float4 v = *(const float4*)(base + (size_t)idx[i] * EE + cc);
        acc.x += v.x; acc.y += v.y; acc.z += v.z; acc.w += v.w;
    }
    *(float4*)(g_mpart + ((size_t)y * BB + b) * HH + tid * 4) = acc;
}

// ---------------- 2b. mean reduce ----------------
__global__ __launch_bounds__(256) void mean_red_kernel()
{
    int b  = blockIdx.x;
    int c4 = threadIdx.x * 4;
    float4 s = make_float4(0.f, 0.f, 0.f, 0.f);
    #pragma unroll
    for (int y = 0; y < SCH; y++) {
        float4 v = *(const float4*)(g_mpart + ((size_t)y * BB + b) * HH + c4);
        s.x += v.x; s.y += v.y; s.z += v.z; s.w += v.w;
    }
    const float inv = 1.0f / SS;
    s.x *= inv; s.y *= inv; s.z *= inv; s.w *= inv;
    *(float4*)(g_mean + b * HH + c4) = s;
}

// ---------------- tf32 split-K GEMM: part[ksplit][64][N] = A@B^T slice ----------------
// A: [64,K] (2 concatenated segments). B: [N,K]. BM=64 BN=128 BK=32.
#define PLDA 36
#define PBUF (64 * PLDA + 128 * PLDA)
#define GTC_SMEM (2 * PBUF * 4)

__global__ __launch_bounds__(256, 1) void gemm64tc_kernel(
    const float* __restrict__ A0, const float* __restrict__ B0, int K0,
    const float* __restrict__ A1, const float* __restrict__ B1, int K1,
    float* __restrict__ part, int N, int kslice)
{
    extern __shared__ float sm[];
    const int tid  = threadIdx.x;
    const int wid  = tid >> 5;
    const int lane = tid & 31;
    const int n0   = blockIdx.x * 128;
    const int kbase = blockIdx.y * kslice;
    const int wm   = wid & 1;
    const int wn   = wid >> 1;
    const int lrow = tid >> 3;
    const int lf4  = tid & 7;

    float d[2][4][4];
    #pragma unroll
    for (int i = 0; i < 2; i++)
        #pragma unroll
        for (int j = 0; j < 4; j++)
            #pragma unroll
            for (int k = 0; k < 4; k++) d[i][j][k] = 0.f;

    auto load_tile = [&](int buf, int gk) {
        const float* A; const float* Bv; int K, kl;
        if (gk < K0) { A = A0; Bv = B0; K = K0; kl = gk; }
        else         { A = A1; Bv = B1; K = K1; kl = gk - K0; }
        float* as = sm + buf * PBUF;
        float* bs = as + 64 * PLDA;
        #pragma unroll
        for (int i = 0; i < 2; i++) {
            int row = lrow + i * 32;
            cp_async16(smem_u32(&as[row * PLDA + lf4 * 4]),
                       &A[(size_t)row * K + kl + lf4 * 4]);
        }
        #pragma unroll
        for (int i = 0; i < 4; i++) {
            int row = lrow + i * 32;
            cp_async16(smem_u32(&bs[row * PLDA + lf4 * 4]),
                       &Bv[(size_t)(n0 + row) * K + kl + lf4 * 4]);
        }
        cp_commit();
    };

    const int NT = kslice / 32;
    load_tile(0, kbase);
    for (int t = 0; t < NT; t++) {
        if (t + 1 < NT) load_tile((t + 1) & 1, kbase + (t + 1) * 32);
        else cp_commit();
        cp_wait1();
        __syncthreads();
        const float* as = sm + (t & 1) * PBUF;
        const float* bs = as + 64 * PLDA;
        const int r = lane >> 2, c = lane & 3;
        #pragma unroll
        for (int k8 = 0; k8 < 4; k8++) {
            int kc = k8 * 8;
            uint32_t af[2][4], bf[4][2];
            #pragma unroll
            for (int mm = 0; mm < 2; mm++) {
                int mb = wm * 32 + mm * 16;
                af[mm][0] = f2tf32(as[(mb + r)     * PLDA + kc + c]);
                af[mm][1] = f2tf32(as[(mb + r + 8) * PLDA + kc + c]);
                af[mm][2] = f2tf32(as[(mb + r)     * PLDA + kc + c + 4]);
                af[mm][3] = f2tf32(as[(mb + r + 8) * PLDA + kc + c + 4]);
            }
            #pragma unroll
            for (int nn = 0; nn < 4; nn++) {
                int nb = wn * 32 + nn * 8;
                bf[nn][0] = f2tf32(bs[(nb + r) * PLDA + kc + c]);
                bf[nn][1] = f2tf32(bs[(nb + r) * PLDA + kc + c + 4]);
            }
            #pragma unroll
            for (int mm = 0; mm < 2; mm++)
                #pragma unroll
                for (int nn = 0; nn < 4; nn++)
                    mma_tf32(d[mm][nn], af[mm], bf[nn]);
        }
        __syncthreads();
    }

    float* dst = part + (size_t)blockIdx.y * 64 * N;
    #pragma unroll
    for (int mm = 0; mm < 2; mm++) {
        int m = wm * 32 + mm * 16 + (lane >> 2);
        #pragma unroll
        for (int nn = 0; nn < 4; nn++) {
            int n = n0 + wn * 32 + nn * 8 + (lane & 3) * 2;
            *(float2*)&dst[(size_t)m * N + n]       = make_float2(d[mm][nn][0], d[mm][nn][1]);
            *(float2*)&dst[(size_t)(m + 8) * N + n] = make_float2(d[mm][nn][2], d[mm][nn][3]);
        }
    }
}

// ---------------- reduce partials + bias (+bias1) (+tanh) ----------------
__global__ __launch_bounds__(256) void reduce_part_kernel(
    const float* __restrict__ bias0, const float* __restrict__ bias1,
    float* __restrict__ C, int N, int do_tanh)
{
    int idx = blockIdx.x * 256 + threadIdx.x;
    int nq = N >> 2;
    int m  = idx / nq;
    int n4 = idx - m * nq;
    float4 s = make_float4(0.f, 0.f, 0.f, 0.f);
    #pragma unroll
    for (int p = 0; p < NSPLIT; p++) {
        float4 v = *(const float4*)&g_part[((size_t)p * 64 + m) * N + n4 * 4];
        s.x += v.x; s.y += v.y; s.z += v.z; s.w += v.w;
    }
    float4 b0 = *(const float4*)&bias0[n4 * 4];
    s.x += b0.x; s.y += b0.y; s.z += b0.z; s.w += b0.w;
    if (bias1) {
        float4 b1 = *(const float4*)&bias1[n4 * 4];
        s.x += b1.x; s.y += b1.y; s.z += b1.z; s.w += b1.w;
    }
    if (do_tanh) {
        s.x = tanhf(s.x); s.y = tanhf(s.y); s.z = tanhf(s.z); s.w = tanhf(s.w);
    }
    *(float4*)&C[(size_t)m * N + n4 * 4] = s;
}

// ---------------- 4a. energies (gather) ----------------
__global__ __launch_bounds__(256) void energy_kernel(
    const int* __restrict__ src, const int* __restrict__ pos,
    const float* __restrict__ emb_in, const float* __restrict__ emb_pos)
{
    __shared__ float h0s[HH];
    int b    = blockIdx.x;
    int tid  = threadIdx.x;
    int warp = tid >> 5;
    int lane = tid & 31;

    for (int c = tid; c < HH; c += 256) h0s[c] = g_h0[b * HH + c];
    __syncthreads();

    int s = blockIdx.y * 8 + warp;
    if (s < SS) {
        int si = __shfl_sync(0xffffffffu, lane == 0 ? src[b * SS + s] : 0, 0);
        int pi = __shfl_sync(0xffffffffu, lane == 0 ? pos[b * SS + s] : 0, 0);
        const float4* rw = (const float4*)(emb_in  + (size_t)si * EE);
        const float4* rp = (const float4*)(emb_pos + (size_t)pi * EE);
        float sum = 0.f;
        #pragma unroll
        for (int e = 0; e < 8; e++) {
            int f4 = lane + e * 32;                 // 0..255
            float4 v = (f4 < 128) ? rw[f4] : rp[f4 - 128];
            int c = f4 * 4;
            sum = fmaf(h0s[c],   v.x, sum);
            sum = fmaf(h0s[c+1], v.y, sum);
            sum = fmaf(h0s[c+2], v.z, sum);
            sum = fmaf(h0s[c+3], v.w, sum);
        }
        #pragma unroll
        for (int o = 16; o; o >>= 1) sum += __shfl_xor_sync(0xffffffffu, sum, o);
        if (lane == 0) g_en[b * SS + s] = sum;
    }
}

// ---------------- 4b. context partials (softmax recomputed in-block, gather) ----------------
__global__ __launch_bounds__(256) void ctx_part_kernel(
    const int* __restrict__ src, const int* __restrict__ pos,
    const float* __restrict__ emb_in, const float* __restrict__ emb_pos)
{
    __shared__ float w[128];
    __shared__ int sidx[32], pidx[32];
    int b    = blockIdx.x;
    int y    = blockIdx.y;
    int tid  = threadIdx.x;
    int lane = tid & 31;
    int s0   = y * (SS / SCH);

    if (tid < 32) {
        // warp 0: softmax over all S (weights include 1/S)
        float e[4];
        float m = -1e30f;
        #pragma unroll
        for (int i = 0; i < 4; i++) {
            int s = lane + i * 32;
            e[i] = (s < SS) ? g_en[b * SS + s] : -1e30f;
            m = fmaxf(m, e[i]);
        }
        #pragma unroll
        for (int o = 16; o; o >>= 1) m = fmaxf(m, __shfl_xor_sync(0xffffffffu, m, o));
        float sum = 0.f;
        #pragma unroll
        for (int i = 0; i < 4; i++) { e[i] = __expf(e[i] - m); sum += e[i]; }
        #pragma unroll
        for (int o = 16; o; o >>= 1) sum += __shfl_xor_sync(0xffffffffu, sum, o);
        float inv = 1.0f / (sum * (float)SS);
        #pragma unroll
        for (int i = 0; i < 4; i++) {
            int s = lane + i * 32;
            if (s < 128) w[s] = e[i] * inv;
        }
    }
    if (tid >= 32 && tid < 32 + SS / SCH) sidx[tid - 32] = src[b * SS + s0 + tid - 32];
    if (tid >= 64 && tid < 64 + SS / SCH) pidx[tid - 64] = pos[b * SS + s0 + tid - 64];
    __syncthreads();

    const int half = tid >= 128;
    const int cc = half ? tid * 4 - EE : tid * 4;
    const float* base = half ? emb_pos : emb_in;
    const int* idx = half ? pidx : sidx;
    float4 acc = make_float4(0.f, 0.f, 0.f, 0.f);
    #pragma unroll 5
    for (int i = 0; i < SS / SCH; i++) {
        float ws = w[s0 + i];
        float4 v = *(const float4*)(base + (size_t)idx[i] * EE + cc);
        acc.x = fmaf(ws, v.x, acc.x); acc.y = fmaf(ws, v.y, acc.y);
        acc.z = fmaf(ws, v.z, acc.z); acc.w = fmaf(ws, v.w, acc.w);
    }
    *(float4*)(g_cpart + ((size_t)y * BB + b) * HH + tid * 4) = acc;
}

// ---------------- 5. build x = [emb_out[tgt] | sum ctx partials] ----------------
__global__ __launch_bounds__(256) void build_x_kernel(
    const int* __restrict__ tgt, const float* __restrict__ emb_out)
{
    int b = blockIdx.x;
    int t = threadIdx.x;
    float4* dst = (float4*)(g_x + b * (EE + HH));
    if (t < 128) {
        const float4* w = (const float4*)(emb_out + (size_t)tgt[b] * EE);
        dst[t] = w[t];
    }
    float4 s = make_float4(0.f, 0.f, 0.f, 0.f);
    #pragma unroll
    for (int y = 0; y < SCH; y++) {
        float4 v = *(const float4*)(g_cpart + ((size_t)y * BB + b) * HH + t * 4);
        s.x += v.x; s.y += v.y; s.z += v.z; s.w += v.w;
    }
    dst[128 + t] = s;
}

// ---------------- 7. projection via mma.sync tf32, 4-stage cp.async ----------------
#define PSTAGES 4
#define PROJ_SMEM (PSTAGES * PBUF * 4)

__global__ __launch_bounds__(256, 1) void proj_mma_kernel(
    const float* __restrict__ A, const float* __restrict__ Bm,
    const float* __restrict__ bias, float* __restrict__ C)
{
    extern __shared__ float sm[];
    const int tid  = threadIdx.x;
    const int wid  = tid >> 5;
    const int lane = tid & 31;
    const int n0   = blockIdx.x * 128;
    const int wm   = wid & 1;
    const int wn   = wid >> 1;
    const int lrow = tid >> 3;
    const int lf4  = tid & 7;

    float d[2][4][4];
    #pragma unroll
    for (int i = 0; i < 2; i++)
        #pragma unroll
        for (int j = 0; j < 4; j++)
            #pragma unroll
            for (int k = 0; k < 4; k++) d[i][j][k] = 0.f;

    auto load_tile = [&](int buf, int kb) {
        float* as = sm + buf * PBUF;
        float* bs = as + 64 * PLDA;
        #pragma unroll
        for (int i = 0; i < 2; i++) {
            int row = lrow + i * 32;
            cp_async16(smem_u32(&as[row * PLDA + lf4 * 4]),
                       &A[(size_t)row * HH + kb + lf4 * 4]);
        }
        #pragma unroll
        for (int i = 0; i < 4; i++) {
            int row = lrow + i * 32;
            cp_async16(smem_u32(&bs[row * PLDA + lf4 * 4]),
                       &Bm[(size_t)(n0 + row) * HH + kb + lf4 * 4]);
        }
        cp_commit();
    };

    const int NT = HH / 32;                           // 32 tiles
    load_tile(0, 0);
    load_tile(1, 32);
    load_tile(2, 64);

    for (int t = 0; t < NT; t++) {
        if (t + 3 < NT) load_tile((t + 3) & (PSTAGES - 1), (t + 3) * 32);
        else cp_commit();
        cp_wait3();
        __syncthreads();

        const float* as = sm + (t & (PSTAGES - 1)) * PBUF;
        const float* bs = as + 64 * PLDA;
        const int r = lane >> 2, c = lane & 3;
        #pragma unroll
        for (int k8 = 0; k8 < 4; k8++) {
            int kc = k8 * 8;
            uint32_t af[2][4], bf[4][2];
            #pragma unroll
            for (int mm = 0; mm < 2; mm++) {
                int mb = wm * 32 + mm * 16;
                af[mm][0] = f2tf32(as[(mb + r)     * PLDA + kc + c]);
                af[mm][1] = f2tf32(as[(mb + r + 8) * PLDA + kc + c]);
                af[mm][2] = f2tf32(as[(mb + r)     * PLDA + kc + c + 4]);
                af[mm][3] = f2tf32(as[(mb + r + 8) * PLDA + kc + c + 4]);
            }
            #pragma unroll
            for (int nn = 0; nn < 4; nn++) {
                int nb = wn * 32 + nn * 8;
                bf[nn][0] = f2tf32(bs[(nb + r) * PLDA + kc + c]);
                bf[nn][1] = f2tf32(bs[(nb + r) * PLDA + kc + c + 4]);
            }
            #pragma unroll
            for (int mm = 0; mm < 2; mm++)
                #pragma unroll
                for (int nn = 0; nn < 4; nn++)
                    mma_tf32(d[mm][nn], af[mm], bf[nn]);
        }
        __syncthreads();
    }

    #pragma unroll
    for (int mm = 0; mm < 2; mm++) {
        int m = wm * 32 + mm * 16 + (lane >> 2);
        #pragma unroll
        for (int nn = 0; nn < 4; nn++) {
            int n = n0 + wn * 32 + nn * 8 + (lane & 3) * 2;
            float2 bv = *(const float2*)&bias[n];
            *(float2*)&C[(size_t)m * VT + n] =
                make_float2(d[mm][nn][0] + bv.x, d[mm][nn][1] + bv.y);
            *(float2*)&C[(size_t)(m + 8) * VT + n] =
                make_float2(d[mm][nn][2] + bv.x, d[mm][nn][3] + bv.y);
        }
    }
}

// ---------------- launch ----------------
extern "C" void kernel_launch(void* const* d_in, const int* in_sizes, int n_in,
                              void* d_out, int out_size)
{
    const int* src = (const int*)d_in[0];
    const int* pos = (const int*)d_in[1];
    const int* tgt = (const int*)d_in[2];

    int iE = -1;
    for (int i = 3; i < n_in; i++) {
        if (in_sizes[i] == 32000 * 512) { iE = i; break; }
    }
    const float* emb_in  = (const float*)d_in[iE + 0];
    const float* emb_out = (const float*)d_in[iE + 1];
    const float* emb_pos = (const float*)d_in[iE + 2];
    const float* W_scale = (const float*)d_in[iE + 3];
    const float* b_scale = (const float*)d_in[iE + 4];
    const float* W_ih    = (const float*)d_in[iE + 5];
    const float* b_ih    = (const float*)d_in[iE + 6];
    const float* W_hh    = (const float*)d_in[iE + 7];
    const float* b_hh    = (const float*)d_in[iE + 8];
    const float* W_proj  = (const float*)d_in[iE + 9];
    const float* b_proj  = (const float*)d_in[iE + 10];

    float* out = (float*)d_out;            // [B,VT]
    float* h   = out + (size_t)BB * VT;    // [B,H]

    float* g_mean_p, *g_x_p, *g_part_p, *g_h0_p;
    cudaGetSymbolAddress((void**)&g_mean_p, g_mean);
    cudaGetSymbolAddress((void**)&g_h0_p,   g_h0);
    cudaGetSymbolAddress((void**)&g_x_p,    g_x);
    cudaGetSymbolAddress((void**)&g_part_p, g_part);

    cudaFuncSetAttribute(proj_mma_kernel,
                         cudaFuncAttributeMaxDynamicSharedMemorySize, PROJ_SMEM);
    cudaFuncSetAttribute(gemm64tc_kernel,
                         cudaFuncAttributeMaxDynamicSharedMemorySize, GTC_SMEM);

    // 2. mean over S (gather partials + reduce)
    mean_part_kernel<<<dim3(BB, SCH), 256>>>(src, pos, emb_in, emb_pos);
    mean_red_kernel<<<BB, 256>>>();
    // 3. h0 = mean @ W_scale^T + b_scale (tf32 split-K)
    gemm64tc_kernel<<<dim3(HH / 128, NSPLIT), 256, GTC_SMEM>>>(
        g_mean_p, W_scale, HH, nullptr, nullptr, 0,
        g_part_p, HH, HH / NSPLIT);
    reduce_part_kernel<<<(64 * HH / 4) / 256, 256>>>(b_scale, nullptr, g_h0_p, HH, 0);
    // 4. attention
    energy_kernel<<<dim3(BB, (SS + 7) / 8), 256>>>(src, pos, emb_in, emb_pos);
    ctx_part_kernel<<<dim3(BB, SCH), 256>>>(src, pos, emb_in, emb_pos);
    // 5. x = [emb_out[tgt] | ctx]
    build_x_kernel<<<BB, 256>>>(tgt, emb_out);
    // 6. h = tanh(x @ W_ih^T + h0 @ W_hh^T + b) (tf32 split-K)
    gemm64tc_kernel<<<dim3(HH / 128, NSPLIT), 256, GTC_SMEM>>>(
        g_x_p, W_ih, EE + HH, g_h0_p, W_hh, HH,
        g_part_p, HH, (EE + HH + HH) / NSPLIT);
    reduce_part_kernel<<<(64 * HH / 4) / 256, 256>>>(b_ih, b_hh, h, HH, 1);
    // 7. out = h @ W_proj^T + b_proj (tf32 mma, 4-stage pipeline)
    proj_mma_kernel<<<VT / 128, 256, PROJ_SMEM>>>(h, W_proj, b_proj, out);

    (void)out_size;
}

// round 6
// speedup vs baseline: 7.9750x; 1.1245x over previous
#include <cuda_runtime.h>
#include <math.h>
#include <stdint.h>

#define BB 64
#define SS 100
#define EE 512
#define HH 1024
#define VT 32000
#define NSPLIT 16
#define SCH 4            // s-chunks for mean/context partials

// ---------------- scratch ----------------
__device__ float g_mpart[SCH * BB * HH];        // mean partials
__device__ float g_mean[BB * HH];
__device__ float g_h0[BB * HH];
__device__ float g_en[BB * SS];                 // energies
__device__ float g_cpart[SCH * BB * HH];        // context partials
__device__ float g_x[BB * (EE + HH)];           // decoder input concat
__device__ float g_part[NSPLIT * BB * HH];      // split-K partials

// ---------------- helpers ----------------
__device__ __forceinline__ uint32_t smem_u32(const void* p) {
    uint32_t a;
    asm("{ .reg .u64 t; cvta.to.shared.u64 t, %1; cvt.u32.u64 %0, t; }" : "=r"(a) : "l"(p));
    return a;
}
__device__ __forceinline__ uint32_t f2tf32(float x) {
    uint32_t u;
    asm("cvt.rna.tf32.f32 %0, %1;" : "=r"(u) : "f"(x));
    return u;
}
__device__ __forceinline__ void cp_async16(uint32_t saddr, const void* g) {
    asm volatile("cp.async.ca.shared.global [%0], [%1], 16;" :: "r"(saddr), "l"(g) : "memory");
}
__device__ __forceinline__ void cp_commit() {
    asm volatile("cp.async.commit_group;" ::: "memory");
}
__device__ __forceinline__ void cp_wait1() {
    asm volatile("cp.async.wait_group 1;" ::: "memory");
}
__device__ __forceinline__ void mma_tf32(float d[4], const uint32_t a[4], const uint32_t b[2]) {
    asm volatile(
        "mma.sync.aligned.m16n8k8.row.col.f32.tf32.tf32.f32 "
        "{%0,%1,%2,%3}, {%4,%5,%6,%7}, {%8,%9}, {%0,%1,%2,%3};"
        : "+f"(d[0]), "+f"(d[1]), "+f"(d[2]), "+f"(d[3])
        : "r"(a[0]), "r"(a[1]), "r"(a[2]), "r"(a[3]), "r"(b[0]), "r"(b[1]));
}

// ---------------- 2a. mean partials (gather directly from embeddings) ----------------
__global__ __launch_bounds__(256) void mean_part_kernel(
    const int* __restrict__ src, const int* __restrict__ pos,
    const float* __restrict__ emb_in, const float* __restrict__ emb_pos)
{
    __shared__ int sidx[32], pidx[32];
    int b   = blockIdx.x;
    int y   = blockIdx.y;
    int tid = threadIdx.x;
    int s0  = y * (SS / SCH);
    if (tid >= 32 && tid < 32 + SS / SCH) sidx[tid - 32] = src[b * SS + s0 + tid - 32];
    if (tid >= 64 && tid < 64 + SS / SCH) pidx[tid - 64] = pos[b * SS + s0 + tid - 64];
    __syncthreads();

    const int half = tid >= 128;
    const int cc = half ? tid * 4 - EE : tid * 4;
    const float* base = half ? emb_pos : emb_in;
    const int* idx = half ? pidx : sidx;
    float4 acc = make_float4(0.f, 0.f, 0.f, 0.f);
    #pragma unroll 5
    for (int i = 0; i < SS / SCH; i++) {
        float4 v = *(const float4*)(base + (size_t)idx[i] * EE + cc);
        acc.x += v.x; acc.y += v.y; acc.z += v.z; acc.w += v.w;
    }
    *(float4*)(g_mpart + ((size_t)y * BB + b) * HH + tid * 4) = acc;
}

// ---------------- 2b. mean reduce ----------------
__global__ __launch_bounds__(256) void mean_red_kernel()
{
    int b  = blockIdx.x;
    int c4 = threadIdx.x * 4;
    float4 s = make_float4(0.f, 0.f, 0.f, 0.f);
    #pragma unroll
    for (int y = 0; y < SCH; y++) {
        float4 v = *(const float4*)(g_mpart + ((size_t)y * BB + b) * HH + c4);
        s.x += v.x; s.y += v.y; s.z += v.z; s.w += v.w;
    }
    const float inv = 1.0f / SS;
    s.x *= inv; s.y *= inv; s.z *= inv; s.w *= inv;
    *(float4*)(g_mean + b * HH + c4) = s;
}

// ---------------- tf32 split-K GEMM: part[ksplit][64][N] = A@B^T slice ----------------
// A: [64,K] (2 concatenated segments). B: [N,K]. BM=64 BN=128 BK=32.
#define PLDA 36
#define PBUF (64 * PLDA + 128 * PLDA)
#define GTC_SMEM (2 * PBUF * 4)

__global__ __launch_bounds__(256, 2) void gemm64tc_kernel(
    const float* __restrict__ A0, const float* __restrict__ B0, int K0,
    const float* __restrict__ A1, const float* __restrict__ B1, int K1,
    float* __restrict__ part, int N, int kslice)
{
    extern __shared__ float sm[];
    const int tid  = threadIdx.x;
    const int wid  = tid >> 5;
    const int lane = tid & 31;
    const int n0   = blockIdx.x * 128;
    const int kbase = blockIdx.y * kslice;
    const int wm   = wid & 1;
    const int wn   = wid >> 1;
    const int lrow = tid >> 3;
    const int lf4  = tid & 7;

    float d[2][4][4];
    #pragma unroll
    for (int i = 0; i < 2; i++)
        #pragma unroll
        for (int j = 0; j < 4; j++)
            #pragma unroll
            for (int k = 0; k < 4; k++) d[i][j][k] = 0.f;

    auto load_tile = [&](int buf, int gk) {
        const float* A; const float* Bv; int K, kl;
        if (gk < K0) { A = A0; Bv = B0; K = K0; kl = gk; }
        else         { A = A1; Bv = B1; K = K1; kl = gk - K0; }
        float* as = sm + buf * PBUF;
        float* bs = as + 64 * PLDA;
        #pragma unroll
        for (int i = 0; i < 2; i++) {
            int row = lrow + i * 32;
            cp_async16(smem_u32(&as[row * PLDA + lf4 * 4]),
                       &A[(size_t)row * K + kl + lf4 * 4]);
        }
        #pragma unroll
        for (int i = 0; i < 4; i++) {
            int row = lrow + i * 32;
            cp_async16(smem_u32(&bs[row * PLDA + lf4 * 4]),
                       &Bv[(size_t)(n0 + row) * K + kl + lf4 * 4]);
        }
        cp_commit();
    };

    const int NT = kslice / 32;
    load_tile(0, kbase);
    for (int t = 0; t < NT; t++) {
        if (t + 1 < NT) load_tile((t + 1) & 1, kbase + (t + 1) * 32);
        else cp_commit();
        cp_wait1();
        __syncthreads();
        const float* as = sm + (t & 1) * PBUF;
        const float* bs = as + 64 * PLDA;
        const int r = lane >> 2, c = lane & 3;
        #pragma unroll
        for (int k8 = 0; k8 < 4; k8++) {
            int kc = k8 * 8;
            uint32_t af[2][4], bf[4][2];
            #pragma unroll
            for (int mm = 0; mm < 2; mm++) {
                int mb = wm * 32 + mm * 16;
                af[mm][0] = f2tf32(as[(mb + r)     * PLDA + kc + c]);
                af[mm][1] = f2tf32(as[(mb + r + 8) * PLDA + kc + c]);
                af[mm][2] = f2tf32(as[(mb + r)     * PLDA + kc + c + 4]);
                af[mm][3] = f2tf32(as[(mb + r + 8) * PLDA + kc + c + 4]);
            }
            #pragma unroll
            for (int nn = 0; nn < 4; nn++) {
                int nb = wn * 32 + nn * 8;
                bf[nn][0] = f2tf32(bs[(nb + r) * PLDA + kc + c]);
                bf[nn][1] = f2tf32(bs[(nb + r) * PLDA + kc + c + 4]);
            }
            #pragma unroll
            for (int mm = 0; mm < 2; mm++)
                #pragma unroll
                for (int nn = 0; nn < 4; nn++)
                    mma_tf32(d[mm][nn], af[mm], bf[nn]);
        }
        __syncthreads();
    }

    float* dst = part + (size_t)blockIdx.y * 64 * N;
    #pragma unroll
    for (int mm = 0; mm < 2; mm++) {
        int m = wm * 32 + mm * 16 + (lane >> 2);
        #pragma unroll
        for (int nn = 0; nn < 4; nn++) {
            int n = n0 + wn * 32 + nn * 8 + (lane & 3) * 2;
            *(float2*)&dst[(size_t)m * N + n]       = make_float2(d[mm][nn][0], d[mm][nn][1]);
            *(float2*)&dst[(size_t)(m + 8) * N + n] = make_float2(d[mm][nn][2], d[mm][nn][3]);
        }
    }
}

// ---------------- reduce partials + bias (+bias1) (+tanh) ----------------
// 4 lanes per float4 output: lane q sums partials 4q..4q+3, quad-shfl combine.
__global__ __launch_bounds__(256) void reduce_part_kernel(
    const float* __restrict__ bias0, const float* __restrict__ bias1,
    float* __restrict__ C, int N, int do_tanh)
{
    const int tid = threadIdx.x;
    const int q   = tid & 3;                       // partial group 0..3
    const int o   = blockIdx.x * 64 + (tid >> 2);  // output float4 index
    const int nq  = N >> 2;
    const int m   = o / nq;
    const int n4  = o - m * nq;

    float4 s = make_float4(0.f, 0.f, 0.f, 0.f);
    #pragma unroll
    for (int i = 0; i < 4; i++) {
        int p = q * 4 + i;
        float4 v = *(const float4*)&g_part[((size_t)p * 64 + m) * N + n4 * 4];
        s.x += v.x; s.y += v.y; s.z += v.z; s.w += v.w;
    }
    // deterministic quad reduction
    #pragma unroll
    for (int off = 2; off >= 1; off >>= 1) {
        s.x += __shfl_down_sync(0xffffffffu, s.x, off, 4);
        s.y += __shfl_down_sync(0xffffffffu, s.y, off, 4);
        s.z += __shfl_down_sync(0xffffffffu, s.z, off, 4);
        s.w += __shfl_down_sync(0xffffffffu, s.w, off, 4);
    }
    if (q == 0) {
        float4 b0 = *(const float4*)&bias0[n4 * 4];
        s.x += b0.x; s.y += b0.y; s.z += b0.z; s.w += b0.w;
        if (bias1) {
            float4 b1 = *(const float4*)&bias1[n4 * 4];
            s.x += b1.x; s.y += b1.y; s.z += b1.z; s.w += b1.w;
        }
        if (do_tanh) {
            s.x = tanhf(s.x); s.y = tanhf(s.y); s.z = tanhf(s.z); s.w = tanhf(s.w);
        }
        *(float4*)&C[(size_t)m * N + n4 * 4] = s;
    }
}

// ---------------- 4a. energies (gather) ----------------
__global__ __launch_bounds__(256) void energy_kernel(
    const int* __restrict__ src, const int* __restrict__ pos,
    const float* __restrict__ emb_in, const float* __restrict__ emb_pos)
{
    __shared__ float h0s[HH];
    int b    = blockIdx.x;
    int tid  = threadIdx.x;
    int warp = tid >> 5;
    int lane = tid & 31;

    for (int c = tid; c < HH; c += 256) h0s[c] = g_h0[b * HH + c];
    __syncthreads();

    int s = blockIdx.y * 8 + warp;
    if (s < SS) {
        int si = __shfl_sync(0xffffffffu, lane == 0 ? src[b * SS + s] : 0, 0);
        int pi = __shfl_sync(0xffffffffu, lane == 0 ? pos[b * SS + s] : 0, 0);
        const float4* rw = (const float4*)(emb_in  + (size_t)si * EE);
        const float4* rp = (const float4*)(emb_pos + (size_t)pi * EE);
        float sum = 0.f;
        #pragma unroll
        for (int e = 0; e < 8; e++) {
            int f4 = lane + e * 32;                 // 0..255
            float4 v = (f4 < 128) ? rw[f4] : rp[f4 - 128];
            int c = f4 * 4;
            sum = fmaf(h0s[c],   v.x, sum);
            sum = fmaf(h0s[c+1], v.y, sum);
            sum = fmaf(h0s[c+2], v.z, sum);
            sum = fmaf(h0s[c+3], v.w, sum);
        }
        #pragma unroll
        for (int o = 16; o; o >>= 1) sum += __shfl_xor_sync(0xffffffffu, sum, o);
        if (lane == 0) g_en[b * SS + s] = sum;
    }
}

// ---------------- 4b. context partials (softmax recomputed in-block, gather) ----------------
__global__ __launch_bounds__(256) void ctx_part_kernel(
    const int* __restrict__ src, const int* __restrict__ pos,
    const float* __restrict__ emb_in, const float* __restrict__ emb_pos)
{
    __shared__ float w[128];
    __shared__ int sidx[32], pidx[32];
    int b    = blockIdx.x;
    int y    = blockIdx.y;
    int tid  = threadIdx.x;
    int lane = tid & 31;
    int s0   = y * (SS / SCH);

    if (tid < 32) {
        float e[4];
        float m = -1e30f;
        #pragma unroll
        for (int i = 0; i < 4; i++) {
            int s = lane + i * 32;
            e[i] = (s < SS) ? g_en[b * SS + s] : -1e30f;
            m = fmaxf(m, e[i]);
        }
        #pragma unroll
        for (int o = 16; o; o >>= 1) m = fmaxf(m, __shfl_xor_sync(0xffffffffu, m, o));
        float sum = 0.f;
        #pragma unroll
        for (int i = 0; i < 4; i++) { e[i] = __expf(e[i] - m); sum += e[i]; }
        #pragma unroll
        for (int o = 16; o; o >>= 1) sum += __shfl_xor_sync(0xffffffffu, sum, o);
        float inv = 1.0f / (sum * (float)SS);
        #pragma unroll
        for (int i = 0; i < 4; i++) {
            int s = lane + i * 32;
            if (s < 128) w[s] = e[i] * inv;
        }
    }
    if (tid >= 32 && tid < 32 + SS / SCH) sidx[tid - 32] = src[b * SS + s0 + tid - 32];
    if (tid >= 64 && tid < 64 + SS / SCH) pidx[tid - 64] = pos[b * SS + s0 + tid - 64];
    __syncthreads();

    const int half = tid >= 128;
    const int cc = half ? tid * 4 - EE : tid * 4;
    const float* base = half ? emb_pos : emb_in;
    const int* idx = half ? pidx : sidx;
    float4 acc = make_float4(0.f, 0.f, 0.f, 0.f);
    #pragma unroll 5
    for (int i = 0; i < SS / SCH; i++) {
        float ws = w[s0 + i];
        float4 v = *(const float4*)(base + (size_t)idx[i] * EE + cc);
        acc.x = fmaf(ws, v.x, acc.x); acc.y = fmaf(ws, v.y, acc.y);
        acc.z = fmaf(ws, v.z, acc.z); acc.w = fmaf(ws, v.w, acc.w);
    }
    *(float4*)(g_cpart + ((size_t)y * BB + b) * HH + tid * 4) = acc;
}

// ---------------- 5. build x = [emb_out[tgt] | sum ctx partials] ----------------
__global__ __launch_bounds__(256) void build_x_kernel(
    const int* __restrict__ tgt, const float* __restrict__ emb_out)
{
    int b = blockIdx.x;
    int t = threadIdx.x;
    float4* dst = (float4*)(g_x + b * (EE + HH));
    if (t < 128) {
        const float4* w = (const float4*)(emb_out + (size_t)tgt[b] * EE);
        dst[t] = w[t];
    }
    float4 s = make_float4(0.f, 0.f, 0.f, 0.f);
    #pragma unroll
    for (int y = 0; y < SCH; y++) {
        float4 v = *(const float4*)(g_cpart + ((size_t)y * BB + b) * HH + t * 4);
        s.x += v.x; s.y += v.y; s.z += v.z; s.w += v.w;
    }
    dst[128 + t] = s;
}

// ---------------- 7. projection via mma.sync tf32, 2-stage, 2 CTA/SM ----------------
#define PROJ_SMEM (2 * PBUF * 4)

__global__ __launch_bounds__(256, 2) void proj_mma_kernel(
    const float* __restrict__ A, const float* __restrict__ Bm,
    const float* __restrict__ bias, float* __restrict__ C)
{
    extern __shared__ float sm[];
    const int tid  = threadIdx.x;
    const int wid  = tid >> 5;
    const int lane = tid & 31;
    const int n0   = blockIdx.x * 128;
    const int wm   = wid & 1;
    const int wn   = wid >> 1;
    const int lrow = tid >> 3;
    const int lf4  = tid & 7;

    float d[2][4][4];
    #pragma unroll
    for (int i = 0; i < 2; i++)
        #pragma unroll
        for (int j = 0; j < 4; j++)
            #pragma unroll
            for (int k = 0; k < 4; k++) d[i][j][k] = 0.f;

    auto load_tile = [&](int buf, int kb) {
        float* as = sm + buf * PBUF;
        float* bs = as + 64 * PLDA;
        #pragma unroll
        for (int i = 0; i < 2; i++) {
            int row = lrow + i * 32;
            cp_async16(smem_u32(&as[row * PLDA + lf4 * 4]),
                       &A[(size_t)row * HH + kb + lf4 * 4]);
        }
        #pragma unroll
        for (int i = 0; i < 4; i++) {
            int row = lrow + i * 32;
            cp_async16(smem_u32(&bs[row * PLDA + lf4 * 4]),
                       &Bm[(size_t)(n0 + row) * HH + kb + lf4 * 4]);
        }
        cp_commit();
    };

    const int NT = HH / 32;                           // 32 tiles
    load_tile(0, 0);
    for (int t = 0; t < NT; t++) {
        if (t + 1 < NT) load_tile((t + 1) & 1, (t + 1) * 32);
        else cp_commit();
        cp_wait1();
        __syncthreads();

        const float* as = sm + (t & 1) * PBUF;
        const float* bs = as + 64 * PLDA;
        const int r = lane >> 2, c = lane & 3;
        #pragma unroll
        for (int k8 = 0; k8 < 4; k8++) {
            int kc = k8 * 8;
            uint32_t af[2][4], bf[4][2];
            #pragma unroll
            for (int mm = 0; mm < 2; mm++) {
                int mb = wm * 32 + mm * 16;
                af[mm][0] = f2tf32(as[(mb + r)     * PLDA + kc + c]);
                af[mm][1] = f2tf32(as[(mb + r + 8) * PLDA + kc + c]);
                af[mm][2] = f2tf32(as[(mb + r)     * PLDA + kc + c + 4]);
                af[mm][3] = f2tf32(as[(mb + r + 8) * PLDA + kc + c + 4]);
            }
            #pragma unroll
            for (int nn = 0; nn < 4; nn++) {
                int nb = wn * 32 + nn * 8;
                bf[nn][0] = f2tf32(bs[(nb + r) * PLDA + kc + c]);
                bf[nn][1] = f2tf32(bs[(nb + r) * PLDA + kc + c + 4]);
            }
            #pragma unroll
            for (int mm = 0; mm < 2; mm++)
                #pragma unroll
                for (int nn = 0; nn < 4; nn++)
                    mma_tf32(d[mm][nn], af[mm], bf[nn]);
        }
        __syncthreads();
    }

    #pragma unroll
    for (int mm = 0; mm < 2; mm++) {
        int m = wm * 32 + mm * 16 + (lane >> 2);
        #pragma unroll
        for (int nn = 0; nn < 4; nn++) {
            int n = n0 + wn * 32 + nn * 8 + (lane & 3) * 2;
            float2 bv = *(const float2*)&bias[n];
            *(float2*)&C[(size_t)m * VT + n] =
                make_float2(d[mm][nn][0] + bv.x, d[mm][nn][1] + bv.y);
            *(float2*)&C[(size_t)(m + 8) * VT + n] =
                make_float2(d[mm][nn][2] + bv.x, d[mm][nn][3] + bv.y);
        }
    }
}

// ---------------- launch ----------------
extern "C" void kernel_launch(void* const* d_in, const int* in_sizes, int n_in,
                              void* d_out, int out_size)
{
    const int* src = (const int*)d_in[0];
    const int* pos = (const int*)d_in[1];
    const int* tgt = (const int*)d_in[2];

    int iE = -1;
    for (int i = 3; i < n_in; i++) {
        if (in_sizes[i] == 32000 * 512) { iE = i; break; }
    }
    const float* emb_in  = (const float*)d_in[iE + 0];
    const float* emb_out = (const float*)d_in[iE + 1];
    const float* emb_pos = (const float*)d_in[iE + 2];
    const float* W_scale = (const float*)d_in[iE + 3];
    const float* b_scale = (const float*)d_in[iE + 4];
    const float* W_ih    = (const float*)d_in[iE + 5];
    const float* b_ih    = (const float*)d_in[iE + 6];
    const float* W_hh    = (const float*)d_in[iE + 7];
    const float* b_hh    = (const float*)d_in[iE + 8];
    const float* W_proj  = (const float*)d_in[iE + 9];
    const float* b_proj  = (const float*)d_in[iE + 10];

    float* out = (float*)d_out;            // [B,VT]
    float* h   = out + (size_t)BB * VT;    // [B,H]

    float* g_mean_p, *g_x_p, *g_part_p, *g_h0_p;
    cudaGetSymbolAddress((void**)&g_mean_p, g_mean);
    cudaGetSymbolAddress((void**)&g_h0_p,   g_h0);
    cudaGetSymbolAddress((void**)&g_x_p,    g_x);
    cudaGetSymbolAddress((void**)&g_part_p, g_part);

    cudaFuncSetAttribute(proj_mma_kernel,
                         cudaFuncAttributeMaxDynamicSharedMemorySize, PROJ_SMEM);
    cudaFuncSetAttribute(gemm64tc_kernel,
                         cudaFuncAttributeMaxDynamicSharedMemorySize, GTC_SMEM);

    const int RED_GRID = (64 * HH / 4) / 64;   // 256 blocks

    // 2. mean over S (gather partials + reduce)
    mean_part_kernel<<<dim3(BB, SCH), 256>>>(src, pos, emb_in, emb_pos);
    mean_red_kernel<<<BB, 256>>>();
    // 3. h0 = mean @ W_scale^T + b_scale (tf32 split-K)
    gemm64tc_kernel<<<dim3(HH / 128, NSPLIT), 256, GTC_SMEM>>>(
        g_mean_p, W_scale, HH, nullptr, nullptr, 0,
        g_part_p, HH, HH / NSPLIT);
    reduce_part_kernel<<<RED_GRID, 256>>>(b_scale, nullptr, g_h0_p, HH, 0);
    // 4. attention
    energy_kernel<<<dim3(BB, (SS + 7) / 8), 256>>>(src, pos, emb_in, emb_pos);
    ctx_part_kernel<<<dim3(BB, SCH), 256>>>(src, pos, emb_in, emb_pos);
    // 5. x = [emb_out[tgt] | ctx]
    build_x_kernel<<<BB, 256>>>(tgt, emb_out);
    // 6. h = tanh(x @ W_ih^T + h0 @ W_hh^T + b) (tf32 split-K)
    gemm64tc_kernel<<<dim3(HH / 128, NSPLIT), 256, GTC_SMEM>>>(
        g_x_p, W_ih, EE + HH, g_h0_p, W_hh, HH,
        g_part_p, HH, (EE + HH + HH) / NSPLIT);
    reduce_part_kernel<<<RED_GRID, 256>>>(b_ih, b_hh, h, HH, 1);
    // 7. out = h @ W_proj^T + b_proj (tf32 mma, 2-stage, 2 CTA/SM)
    proj_mma_kernel<<<VT / 128, 256, PROJ_SMEM>>>(h, W_proj, b_proj, out);

    (void)out_size;
}